// round 1
// baseline (speedup 1.0000x reference)
#include <cuda_runtime.h>
#include <math.h>
#include <stdint.h>

#define NB 512
#define NC 151
#define IN_DIM 4096
#define NMS_T 0.3f

// ---- scratch (no allocations allowed) ----
#define KS 32            // k-splits
#define BKS (IN_DIM/KS)  // 128
#define BN 160           // padded N

__device__ float    g_part[KS * NB * BN];        // split-K partials
__device__ float    g_scores[NC * NB];           // scores transposed [c][b]
__device__ unsigned g_masks[NC * 16 * NB];       // [c][word][row]
__device__ float    g_rowmax[NB];
__device__ int      g_rowarg[NB];

// ---------------- GEMM: partial (split-K, deterministic) ----------------
__global__ void gemm_partial(const float* __restrict__ A, const float* __restrict__ W) {
    __shared__ float As[8][65];
    __shared__ float Bs[8][BN];
    const int mt = blockIdx.x;       // 0..7 (64 rows each)
    const int ks = blockIdx.y;       // 0..31
    const int tid = threadIdx.x;     // 256
    const int tx = tid & 15, ty = tid >> 4;
    const int k0 = ks * BKS;

    float acc[4][10];
#pragma unroll
    for (int i = 0; i < 4; i++)
#pragma unroll
        for (int j = 0; j < 10; j++) acc[i][j] = 0.0f;

    for (int kc = 0; kc < BKS; kc += 8) {
        // load A tile 64x8
#pragma unroll
        for (int r = 0; r < 2; r++) {
            int idx = tid + r * 256;
            int m = idx >> 3, kk = idx & 7;
            As[kk][m] = A[(mt * 64 + m) * IN_DIM + k0 + kc + kk];
        }
        // load W tile 8x160 (guard n<151)
#pragma unroll
        for (int r = 0; r < 5; r++) {
            int idx = tid + r * 256;
            int kk = idx / BN, n = idx % BN;
            Bs[kk][n] = (n < NC) ? W[(k0 + kc + kk) * NC + n] : 0.0f;
        }
        __syncthreads();
#pragma unroll
        for (int kk = 0; kk < 8; kk++) {
            float a[4], b[10];
#pragma unroll
            for (int i = 0; i < 4; i++) a[i] = As[kk][ty * 4 + i];
#pragma unroll
            for (int j = 0; j < 10; j++) b[j] = Bs[kk][tx * 10 + j];
#pragma unroll
            for (int i = 0; i < 4; i++)
#pragma unroll
                for (int j = 0; j < 10; j++) acc[i][j] = fmaf(a[i], b[j], acc[i][j]);
        }
        __syncthreads();
    }
#pragma unroll
    for (int i = 0; i < 4; i++) {
        int m = mt * 64 + ty * 4 + i;
#pragma unroll
        for (int j = 0; j < 10; j++) {
            int n = tx * 10 + j;
            g_part[(ks * NB + m) * BN + n] = acc[i][j];
        }
    }
}

// ---------------- GEMM: fixed-order reduction + bias ----------------
__global__ void gemm_reduce(const float* __restrict__ bias, float* __restrict__ out) {
    int idx = blockIdx.x * 256 + threadIdx.x;
    if (idx >= NB * NC) return;
    int m = idx / NC, n = idx % NC;
    float s = 0.0f;
#pragma unroll 8
    for (int ks = 0; ks < KS; ks++) s += g_part[(ks * NB + m) * BN + n];
    out[idx] = s + bias[n];
}

// ---------------- softmax per row -> scores_t [c][b], rowmax/rowarg ----------------
__global__ void softmax_kernel(const float* __restrict__ dists) {
    const int b = blockIdx.x;
    const int t = threadIdx.x;   // 256
    __shared__ float sred[256];
    __shared__ int   sidx[256];

    float d = (t < NC) ? dists[b * NC + t] : -INFINITY;
    sred[t] = d;
    __syncthreads();
    for (int off = 128; off; off >>= 1) {
        if (t < off) sred[t] = fmaxf(sred[t], sred[t + off]);
        __syncthreads();
    }
    float m = sred[0];
    __syncthreads();

    float e = (t < NC) ? expf(__fsub_rn(d, m)) : 0.0f;
    sred[t] = e;
    __syncthreads();
    for (int off = 128; off; off >>= 1) {
        if (t < off) sred[t] = __fadd_rn(sred[t], sred[t + off]);
        __syncthreads();
    }
    float s = sred[0];
    __syncthreads();

    float sc = -INFINITY;
    if (t < NC) {
        sc = (t == 0) ? 0.0f : __fdiv_rn(e, s);
        g_scores[t * NB + b] = sc;
    }
    // row argmax (ties -> lowest class)
    sred[t] = sc; sidx[t] = t;
    __syncthreads();
    for (int off = 128; off; off >>= 1) {
        if (t < off) {
            float ov = sred[t + off]; int oi = sidx[t + off];
            if (ov > sred[t] || (ov == sred[t] && oi < sidx[t])) { sred[t] = ov; sidx[t] = oi; }
        }
        __syncthreads();
    }
    if (t == 0) { g_rowmax[b] = sred[0]; g_rowarg[b] = sidx[0]; }
}

// ---------------- per-class pairwise IoU bitmasks ----------------
// Unfused fp ops to match the reference's elementwise arithmetic exactly.
__global__ void mask_kernel(const float* __restrict__ boxes) {
    const int c = blockIdx.x;     // class
    const int t = threadIdx.x;    // 512, row (pivot) index
    __shared__ float X1[NB], Y1[NB], X2[NB], Y2[NB], AR[NB];

    const float4 v = ((const float4*)boxes)[t * NC + c];
    float w = __fadd_rn(__fsub_rn(v.z, v.x), 1.0f);
    float h = __fadd_rn(__fsub_rn(v.w, v.y), 1.0f);
    float ar = __fmul_rn(w, h);
    X1[t] = v.x; Y1[t] = v.y; X2[t] = v.z; Y2[t] = v.w; AR[t] = ar;
    __syncthreads();

    unsigned word = 0;
    for (int j = 0; j < NB; j++) {
        float ix1 = fmaxf(v.x, X1[j]);
        float iy1 = fmaxf(v.y, Y1[j]);
        float ix2 = fminf(v.z, X2[j]);
        float iy2 = fminf(v.w, Y2[j]);
        float iw = fmaxf(__fadd_rn(__fsub_rn(ix2, ix1), 1.0f), 0.0f);
        float ih = fmaxf(__fadd_rn(__fsub_rn(iy2, iy1), 1.0f), 0.0f);
        float inter = __fmul_rn(iw, ih);
        float uni = __fsub_rn(__fadd_rn(ar, AR[j]), inter);
        float iou = __fdiv_rn(inter, uni);
        if (iou >= NMS_T) word |= (1u << (j & 31));
        if ((j & 31) == 31) {
            g_masks[(c * 16 + (j >> 5)) * NB + t] = word;
            word = 0;
        }
    }
}

// ---------------- sequential greedy NMS decode (single block) ----------------
__global__ void __launch_bounds__(512, 1) nms_kernel(float* __restrict__ out) {
    __shared__ float rmax[NB];
    __shared__ int   rarg[NB];
    __shared__ int   commits[NB];
    __shared__ float wval[16];
    __shared__ int   widx[16];
    __shared__ int   s_box, s_cls, s_nmark;
    __shared__ int   marked[NB];

    const int t = threadIdx.x;
    const int lane = t & 31, wid = t >> 5;

    rmax[t] = g_rowmax[t];
    rarg[t] = g_rowarg[t];
    commits[t] = 0;
    __syncthreads();

    for (int iter = 0; iter < NB; iter++) {
        if (t == 0) s_nmark = 0;
        // global argmax over rowmax (ties -> lowest box)
        float v = rmax[t]; int idx = t;
#pragma unroll
        for (int off = 16; off; off >>= 1) {
            float ov = __shfl_down_sync(0xffffffffu, v, off);
            int   oi = __shfl_down_sync(0xffffffffu, idx, off);
            if (ov > v || (ov == v && oi < idx)) { v = ov; idx = oi; }
        }
        if (lane == 0) { wval[wid] = v; widx[wid] = idx; }
        __syncthreads();
        if (wid == 0) {
            float v2 = (lane < 16) ? wval[lane] : -INFINITY;
            int   i2 = (lane < 16) ? widx[lane] : 0x7fffffff;
#pragma unroll
            for (int off = 16; off; off >>= 1) {
                float ov = __shfl_down_sync(0xffffffffu, v2, off);
                int   oi = __shfl_down_sync(0xffffffffu, i2, off);
                if (ov > v2 || (ov == v2 && oi < i2)) { v2 = ov; i2 = oi; }
            }
            if (lane == 0) {
                int box = i2;
                int cls = rarg[box];
                s_box = box; s_cls = cls;
                commits[box] = cls;
            }
        }
        __syncthreads();
        const int box = s_box, cls = s_cls;

        // column update: zero scores[:, cls] where overlapping pivot
        unsigned word = g_masks[(cls * 16 + wid) * NB + box];
        if ((word >> lane) & 1u) {
            if (t != box) {
                float old = g_scores[cls * NB + t];
                if (old != 0.0f) {
                    g_scores[cls * NB + t] = 0.0f;
                    if (old > 0.0f) {
                        if (rarg[t] == cls) {          // this row's max was zeroed -> rescan
                            int p = atomicAdd(&s_nmark, 1);
                            marked[p] = t;
                        }
                    } else {                           // retired row (-1) resurrected to 0
                        if (rmax[t] < 0.0f) { rmax[t] = 0.0f; rarg[t] = cls; }
                        else if (rmax[t] == 0.0f && cls < rarg[t]) { rarg[t] = cls; }
                    }
                }
            }
        }
        // retire pivot row
        if (t < NC) g_scores[t * NB + box] = -1.0f;
        if (t == box) { rmax[t] = -1.0f; rarg[t] = 0; }
        __syncthreads();

        // rescans: one warp per marked row
        const int nm = s_nmark;
        for (int i = wid; i < nm; i += 16) {
            int m = marked[i];
            float bv = -INFINITY; int bc = 0x7fffffff;
            for (int c = lane; c < NC; c += 32) {
                float sv = g_scores[c * NB + m];
                if (sv > bv) { bv = sv; bc = c; }     // ascending c -> keeps lowest on ties
            }
#pragma unroll
            for (int off = 16; off; off >>= 1) {
                float ov = __shfl_down_sync(0xffffffffu, bv, off);
                int   oc = __shfl_down_sync(0xffffffffu, bc, off);
                if (ov > bv || (ov == bv && oc < bc)) { bv = ov; bc = oc; }
            }
            if (lane == 0) { rmax[m] = bv; rarg[m] = bc; }
        }
        __syncthreads();
    }

    out[NB * NC + t] = (float)commits[t];
}

// ---------------- launch ----------------
extern "C" void kernel_launch(void* const* d_in, const int* in_sizes, int n_in,
                              void* d_out, int out_size) {
    const float* obj_fmap = (const float*)d_in[0];   // [512,4096]
    const float* boxes    = (const float*)d_in[1];   // [512,151,4]
    const float* W        = (const float*)d_in[2];   // [4096,151]
    const float* b        = (const float*)d_in[3];   // [151]
    float* out = (float*)d_out;                      // 77312 dists + 512 preds

    gemm_partial<<<dim3(8, KS), 256>>>(obj_fmap, W);
    gemm_reduce<<<(NB * NC + 255) / 256, 256>>>(b, out);
    softmax_kernel<<<NB, 256>>>(out);
    mask_kernel<<<NC, NB>>>(boxes);
    nms_kernel<<<1, NB>>>(out);
}

// round 2
// speedup vs baseline: 1.1511x; 1.1511x over previous
#include <cuda_runtime.h>
#include <math.h>
#include <stdint.h>

#define NB 512
#define NC 151
#define IN_DIM 4096
#define NMS_T 0.3f

#define KS 32            // k-splits
#define BKS (IN_DIM/KS)  // 128
#define BN 160           // padded N

// ---- device scratch (no allocations allowed) ----
__device__ float    g_part[KS * NB * BN];        // split-K partials
__device__ float    g_scores_rm[NB * NC];        // row-major softmax scores
__device__ unsigned g_masks[NC * 16 * NB];       // [c][word][x]: bit l of word w at x = overlap(32w+l, x)
__device__ float    g_rowmax[NB];
__device__ int      g_rowarg[NB];
__device__ float    g_r2max[NB];
__device__ int      g_r2arg[NB];

// monotonic-uint mapping for float compare (handles the -1 sentinel)
__device__ __forceinline__ unsigned fmono(float v) {
    unsigned b = __float_as_uint(v);
    return (b & 0x80000000u) ? ~b : (b | 0x80000000u);
}

// =================== fused: GEMM split-K partials + IoU masks ===================
__global__ void __launch_bounds__(256) fused_gemm_mask(
    const float* __restrict__ A, const float* __restrict__ W,
    const float* __restrict__ boxes)
{
    __shared__ union {
        struct { float As[8][65]; float Bs[8][BN]; } g;
        struct { float4 box[NB]; float area[NB]; } m;
    } sm;
    const int tid = threadIdx.x;

    if (blockIdx.x < NC) {
        // ---------------- mask path: one class per block ----------------
        const int c = blockIdx.x;
        const int lane = tid & 31, w = tid >> 5;
        for (int i = tid; i < NB; i += 256) {
            float4 v = ((const float4*)boxes)[i * NC + c];
            float bw = __fadd_rn(__fsub_rn(v.z, v.x), 1.0f);
            float bh = __fadd_rn(__fsub_rn(v.w, v.y), 1.0f);
            sm.m.box[i] = v;
            sm.m.area[i] = __fmul_rn(bw, bh);
        }
        __syncthreads();

#pragma unroll
        for (int half = 0; half < 2; half++) {
            const int p = ((w + 8 * half) << 5) + lane;   // pivot row
            const float4 pv = sm.m.box[p];
            const float par = sm.m.area[p];
            unsigned* gbase = &g_masks[(c * 16 + (p >> 5)) * NB];
            for (int j = 0; j < NB; j++) {
                float4 bv = sm.m.box[j];
                float baj = sm.m.area[j];
                float ix1 = fmaxf(pv.x, bv.x);
                float iy1 = fmaxf(pv.y, bv.y);
                float ix2 = fminf(pv.z, bv.z);
                float iy2 = fminf(pv.w, bv.w);
                float iw = fmaxf(__fadd_rn(__fsub_rn(ix2, ix1), 1.0f), 0.0f);
                float ih = fmaxf(__fadd_rn(__fsub_rn(iy2, iy1), 1.0f), 0.0f);
                float inter = __fmul_rn(iw, ih);
                float uni = __fsub_rn(__fadd_rn(par, baj), inter);
                // fast predicate with exact fallback near threshold (bit-identical result)
                float t3 = __fmul_rn(NMS_T, uni);
                float diff = inter - t3;
                bool pred = diff > 0.0f;
                bool near = fabsf(diff) <= 1e-4f * t3;
                if (__any_sync(0xffffffffu, near)) {
                    float q = __fdiv_rn(inter, uni);
                    if (near) pred = (q >= NMS_T);
                }
                unsigned word = __ballot_sync(0xffffffffu, pred);
                if (lane == 0) gbase[j] = word;
            }
        }
    } else {
        // ---------------- gemm path (identical numerics to round 1) ----------------
        const int bi = blockIdx.x - NC;
        const int mt = bi >> 5;          // 0..7
        const int ks = bi & 31;          // 0..31
        const int tx = tid & 15, ty = tid >> 4;
        const int k0 = ks * BKS;

        float acc[4][10];
#pragma unroll
        for (int i = 0; i < 4; i++)
#pragma unroll
            for (int j = 0; j < 10; j++) acc[i][j] = 0.0f;

        for (int kc = 0; kc < BKS; kc += 8) {
#pragma unroll
            for (int r = 0; r < 2; r++) {
                int idx = tid + r * 256;
                int m = idx >> 3, kk = idx & 7;
                sm.g.As[kk][m] = A[(mt * 64 + m) * IN_DIM + k0 + kc + kk];
            }
#pragma unroll
            for (int r = 0; r < 5; r++) {
                int idx = tid + r * 256;
                int kk = idx / BN, n = idx % BN;
                sm.g.Bs[kk][n] = (n < NC) ? W[(k0 + kc + kk) * NC + n] : 0.0f;
            }
            __syncthreads();
#pragma unroll
            for (int kk = 0; kk < 8; kk++) {
                float a[4], b[10];
#pragma unroll
                for (int i = 0; i < 4; i++) a[i] = sm.g.As[kk][ty * 4 + i];
#pragma unroll
                for (int j = 0; j < 10; j++) b[j] = sm.g.Bs[kk][tx * 10 + j];
#pragma unroll
                for (int i = 0; i < 4; i++)
#pragma unroll
                    for (int j = 0; j < 10; j++) acc[i][j] = fmaf(a[i], b[j], acc[i][j]);
            }
            __syncthreads();
        }
#pragma unroll
        for (int i = 0; i < 4; i++) {
            int m = mt * 64 + ty * 4 + i;
#pragma unroll
            for (int j = 0; j < 10; j++) {
                int n = tx * 10 + j;
                g_part[(ks * NB + m) * BN + n] = acc[i][j];
            }
        }
    }
}

// =================== reduce + bias + softmax + top-2 ===================
__global__ void __launch_bounds__(256) softmax_kernel(const float* __restrict__ bias,
                                                      float* __restrict__ out)
{
    const int b = blockIdx.x;
    const int t = threadIdx.x;
    __shared__ float sred[256];
    __shared__ int   sidx[256];

    float d = -INFINITY;
    if (t < NC) {
        float s = 0.0f;
#pragma unroll 8
        for (int ks = 0; ks < KS; ks++) s += g_part[(ks * NB + b) * BN + t];
        d = s + bias[t];
        out[b * NC + t] = d;
    }
    sred[t] = d;
    __syncthreads();
    for (int off = 128; off; off >>= 1) {
        if (t < off) sred[t] = fmaxf(sred[t], sred[t + off]);
        __syncthreads();
    }
    float m = sred[0];
    __syncthreads();

    float e = (t < NC) ? expf(__fsub_rn(d, m)) : 0.0f;
    sred[t] = e;
    __syncthreads();
    for (int off = 128; off; off >>= 1) {
        if (t < off) sred[t] = __fadd_rn(sred[t], sred[t + off]);
        __syncthreads();
    }
    float s = sred[0];
    __syncthreads();

    float sc = -INFINITY;
    if (t < NC) {
        sc = (t == 0) ? 0.0f : __fdiv_rn(e, s);
        g_scores_rm[b * NC + t] = sc;
    }
    // top-1 (ties -> lowest class)
    sred[t] = sc; sidx[t] = t;
    __syncthreads();
    for (int off = 128; off; off >>= 1) {
        if (t < off) {
            float ov = sred[t + off]; int oi = sidx[t + off];
            if (ov > sred[t] || (ov == sred[t] && oi < sidx[t])) { sred[t] = ov; sidx[t] = oi; }
        }
        __syncthreads();
    }
    int a1 = sidx[0];
    float v1 = sred[0];
    if (t == 0) { g_rowmax[b] = v1; g_rowarg[b] = a1; }
    __syncthreads();
    // top-2 excluding a1
    sred[t] = (t == a1) ? -INFINITY : sc;
    sidx[t] = t;
    __syncthreads();
    for (int off = 128; off; off >>= 1) {
        if (t < off) {
            float ov = sred[t + off]; int oi = sidx[t + off];
            if (ov > sred[t] || (ov == sred[t] && oi < sidx[t])) { sred[t] = ov; sidx[t] = oi; }
        }
        __syncthreads();
    }
    if (t == 0) { g_r2max[b] = sred[0]; g_r2arg[b] = sidx[0]; }
}

// =================== sequential greedy NMS (single block, SMEM state) ===================
__global__ void __launch_bounds__(256, 1) nms_kernel(float* __restrict__ out)
{
    __shared__ float rmax[NB];
    __shared__ int   rarg[NB];
    __shared__ float r2max[NB];
    __shared__ int   r2arg[NB];
    __shared__ unsigned zb[NB * 5];          // per-row zeroed-class bitset
    __shared__ unsigned char retired[NB];
    __shared__ int   commits[NB];
    __shared__ unsigned long long wkey[8];
    __shared__ int   s_box, s_cls, s_nm;
    __shared__ short marked[NB];

    const int t = threadIdx.x;
    const int lane = t & 31, w = t >> 5;

#pragma unroll
    for (int half = 0; half < 2; half++) {
        int r = t + 256 * half;
        rmax[r] = g_rowmax[r]; rarg[r] = g_rowarg[r];
        r2max[r] = g_r2max[r]; r2arg[r] = g_r2arg[r];
        retired[r] = 0; commits[r] = 0;
#pragma unroll
        for (int k = 0; k < 5; k++) zb[r * 5 + k] = 0;
    }
    __syncthreads();

    for (int iter = 0; iter < NB; iter++) {
        // ---- global argmax over rows (ties -> lowest box index) ----
        unsigned long long k0 = ((unsigned long long)fmono(rmax[t]) << 32) | (unsigned)(NB - 1 - t);
        unsigned long long k1 = ((unsigned long long)fmono(rmax[t + 256]) << 32) | (unsigned)(NB - 1 - (t + 256));
        unsigned long long k = k0 > k1 ? k0 : k1;
#pragma unroll
        for (int off = 16; off; off >>= 1) {
            unsigned long long o = __shfl_down_sync(0xffffffffu, k, off);
            if (o > k) k = o;
        }
        if (lane == 0) wkey[w] = k;
        __syncthreads();
        if (t == 0) {
            unsigned long long best = wkey[0];
#pragma unroll
            for (int i = 1; i < 8; i++) if (wkey[i] > best) best = wkey[i];
            int box = NB - 1 - (int)(best & 0xffffffffu);
            int cls = rarg[box];
            s_box = box; s_cls = cls; s_nm = 0;
            commits[box] = cls;
        }
        __syncthreads();
        const int box = s_box, cls = s_cls;
        const int cwbase = cls * 16;
        const unsigned cbm = 1u << (cls & 31);
        const int cwi = cls >> 5;

        // ---- state update (SMEM-only; one mask word from L2 per row-half) ----
#pragma unroll
        for (int half = 0; half < 2; half++) {
            int r = t + 256 * half;
            unsigned word = g_masks[(cwbase + (r >> 5)) * NB + box];
            bool hit = (word >> (r & 31)) & 1u;
            if (r == box) {
                retired[r] = 1; rmax[r] = -1.0f; rarg[r] = 0; r2arg[r] = -1;
#pragma unroll
                for (int kk = 0; kk < 5; kk++) zb[r * 5 + kk] = 0;
            } else if (hit) {
                unsigned zw = zb[r * 5 + cwi];
                if (retired[r]) {
                    if (!(zw & cbm)) {           // -1 -> 0 resurrection
                        zb[r * 5 + cwi] = zw | cbm;
                        if (rmax[r] < 0.0f) { rmax[r] = 0.0f; rarg[r] = cls; }
                        else if (cls < rarg[r]) rarg[r] = cls;
                    }
                } else if (cls != 0 && !(zw & cbm)) {
                    zb[r * 5 + cwi] = zw | cbm;  // positive -> 0
                    if (cls == rarg[r]) {
                        int sa = r2arg[r];
                        if (sa >= 0) { rmax[r] = r2max[r]; rarg[r] = sa; r2arg[r] = -1; }
                        else marked[atomicAdd(&s_nm, 1)] = (short)r;
                    } else if (cls == r2arg[r]) {
                        r2arg[r] = -1;
                    }
                }
            }
        }
        __syncthreads();

        // ---- rescans (rare): recompute top-2 of effective row ----
        const int nm = s_nm;
        for (int i = w; i < nm; i += 8) {
            int mrow = marked[i];
            const float* rowp = g_scores_rm + mrow * NC;
            float v1 = -1e30f, v2 = -1e30f; int c1 = 0x7fff, c2 = 0x7fff;
            for (int c = lane; c < NC; c += 32) {
                float v = rowp[c];
                if (c == 0 || ((zb[mrow * 5 + (c >> 5)] >> (c & 31)) & 1u)) v = 0.0f;
                if (v > v1) { v2 = v1; c2 = c1; v1 = v; c1 = c; }
                else if (v > v2) { v2 = v; c2 = c; }
            }
#pragma unroll
            for (int off = 16; off; off >>= 1) {
                float o1 = __shfl_down_sync(0xffffffffu, v1, off);
                float o2 = __shfl_down_sync(0xffffffffu, v2, off);
                int  oc1 = __shfl_down_sync(0xffffffffu, c1, off);
                int  oc2 = __shfl_down_sync(0xffffffffu, c2, off);
                float cv; int cc;
                if (o1 > v1 || (o1 == v1 && oc1 < c1)) { cv = v1; cc = c1; v1 = o1; c1 = oc1; }
                else { cv = o1; cc = oc1; }
                if (cv > v2 || (cv == v2 && cc < c2)) { v2 = cv; c2 = cc; }
                if (o2 > v2 || (o2 == v2 && oc2 < c2)) { v2 = o2; c2 = oc2; }
            }
            if (lane == 0) {
                rmax[mrow] = v1; rarg[mrow] = c1;
                r2max[mrow] = v2; r2arg[mrow] = c2;
            }
        }
        __syncthreads();
    }

#pragma unroll
    for (int half = 0; half < 2; half++) {
        int r = t + 256 * half;
        out[NB * NC + r] = (float)commits[r];
    }
}

// =================== launch ===================
extern "C" void kernel_launch(void* const* d_in, const int* in_sizes, int n_in,
                              void* d_out, int out_size) {
    const float* obj_fmap = (const float*)d_in[0];   // [512,4096]
    const float* boxes    = (const float*)d_in[1];   // [512,151,4]
    const float* W        = (const float*)d_in[2];   // [4096,151]
    const float* b        = (const float*)d_in[3];   // [151]
    float* out = (float*)d_out;                      // 77312 dists + 512 preds

    fused_gemm_mask<<<NC + 256, 256>>>(obj_fmap, W, boxes);
    softmax_kernel<<<NB, 256>>>(b, out);
    nms_kernel<<<1, 256>>>(out);
}

// round 4
// speedup vs baseline: 1.2365x; 1.0742x over previous
#include <cuda_runtime.h>
#include <math.h>
#include <stdint.h>

#define NB 512
#define NC 151
#define IN_DIM 4096
#define NMS_T 0.3f

#define KS 32            // k-splits
#define BKS (IN_DIM/KS)  // 128
#define BN 160           // padded N

// ---- device scratch (no allocations allowed) ----
__device__ float    g_part[KS * NB * BN];        // split-K partials
__device__ float    g_scores_rm[NB * NC];        // row-major softmax scores
__device__ unsigned g_masks16[NC * NB * 16];     // [c][box][w]: bit l of w = overlap(32w+l, box)
__device__ float    g_rowmax[NB];
__device__ int      g_rowarg[NB];
__device__ float    g_r2max[NB];
__device__ int      g_r2arg[NB];

// monotonic-uint mapping for float compare (handles the -1 sentinel)
__device__ __forceinline__ unsigned fmono(float v) {
    unsigned b = __float_as_uint(v);
    return (b & 0x80000000u) ? ~b : (b | 0x80000000u);
}

// =================== fused: GEMM split-K partials + symmetric IoU masks ===================
__global__ void __launch_bounds__(256) fused_gemm_mask(
    const float* __restrict__ A, const float* __restrict__ W,
    const float* __restrict__ boxes)
{
    __shared__ union {
        struct { float As[8][65]; float Bs[8][BN]; } g;
        struct { float4 box[NB]; float area[NB]; } m;
    } sm;
    const int tid = threadIdx.x;

    if (blockIdx.x < NC) {
        // ---------------- mask path: one class per block, symmetric tiles ----------------
        const int c = blockIdx.x;
        const int lane = tid & 31, w = tid >> 5;
        for (int i = tid; i < NB; i += 256) {
            float4 v = ((const float4*)boxes)[i * NC + c];
            float bw = __fadd_rn(__fsub_rn(v.z, v.x), 1.0f);
            float bh = __fadd_rn(__fsub_rn(v.w, v.y), 1.0f);
            sm.m.box[i] = v;
            sm.m.area[i] = __fmul_rn(bw, bh);
        }
        __syncthreads();

        unsigned* gb = &g_masks16[(size_t)c * NB * 16];
        int tcnt = 0;
        for (int pb = 0; pb < 16; pb++) {
            for (int jb = pb; jb < 16; jb++, tcnt++) {
                if ((tcnt & 7) != w) continue;
                const int p = (pb << 5) + lane;
                const float4 pv = sm.m.box[p];
                const float par = sm.m.area[p];
                unsigned bword = 0, tmask = 0;
                for (int jj = 0; jj < 32; jj++) {
                    int j = (jb << 5) + jj;
                    float4 bv = sm.m.box[j];
                    float baj = sm.m.area[j];
                    float ix1 = fmaxf(pv.x, bv.x);
                    float iy1 = fmaxf(pv.y, bv.y);
                    float ix2 = fminf(pv.z, bv.z);
                    float iy2 = fminf(pv.w, bv.w);
                    float iw = fmaxf(__fadd_rn(__fsub_rn(ix2, ix1), 1.0f), 0.0f);
                    float ih = fmaxf(__fadd_rn(__fsub_rn(iy2, iy1), 1.0f), 0.0f);
                    float inter = __fmul_rn(iw, ih);
                    float uni = __fsub_rn(__fadd_rn(par, baj), inter);
                    float t3 = __fmul_rn(NMS_T, uni);
                    float diff = inter - t3;
                    bool pred = diff > 0.0f;
                    bool near = fabsf(diff) <= 1e-4f * t3;
                    if (__any_sync(0xffffffffu, near)) {
                        float q = __fdiv_rn(inter, uni);
                        if (near) pred = (q >= NMS_T);
                    }
                    unsigned word = __ballot_sync(0xffffffffu, pred);
                    if (lane == jj) bword = word;
                    tmask |= ((unsigned)pred) << jj;
                }
                gb[(((jb << 5) + lane) << 4) + pb] = bword;     // boxes in jb, pivot-bits pb
                if (jb != pb)
                    gb[(((pb << 5) + lane) << 4) + jb] = tmask; // boxes in pb, j-bits jb (symmetry)
            }
        }
    } else {
        // ---------------- gemm path (identical numerics) ----------------
        const int bi = blockIdx.x - NC;
        const int mt = bi >> 5;          // 0..7
        const int ks = bi & 31;          // 0..31
        const int tx = tid & 15, ty = tid >> 4;
        const int k0 = ks * BKS;

        float acc[4][10];
#pragma unroll
        for (int i = 0; i < 4; i++)
#pragma unroll
            for (int j = 0; j < 10; j++) acc[i][j] = 0.0f;

        for (int kc = 0; kc < BKS; kc += 8) {
#pragma unroll
            for (int r = 0; r < 2; r++) {
                int idx = tid + r * 256;
                int m = idx >> 3, kk = idx & 7;
                sm.g.As[kk][m] = A[(mt * 64 + m) * IN_DIM + k0 + kc + kk];
            }
#pragma unroll
            for (int r = 0; r < 5; r++) {
                int idx = tid + r * 256;
                int kk = idx / BN, n = idx % BN;
                sm.g.Bs[kk][n] = (n < NC) ? W[(k0 + kc + kk) * NC + n] : 0.0f;
            }
            __syncthreads();
#pragma unroll
            for (int kk = 0; kk < 8; kk++) {
                float a[4], b[10];
#pragma unroll
                for (int i = 0; i < 4; i++) a[i] = sm.g.As[kk][ty * 4 + i];
#pragma unroll
                for (int j = 0; j < 10; j++) b[j] = sm.g.Bs[kk][tx * 10 + j];
#pragma unroll
                for (int i = 0; i < 4; i++)
#pragma unroll
                    for (int j = 0; j < 10; j++) acc[i][j] = fmaf(a[i], b[j], acc[i][j]);
            }
            __syncthreads();
        }
#pragma unroll
        for (int i = 0; i < 4; i++) {
            int m = mt * 64 + ty * 4 + i;
#pragma unroll
            for (int j = 0; j < 10; j++) {
                int n = tx * 10 + j;
                g_part[(ks * NB + m) * BN + n] = acc[i][j];
            }
        }
    }
}

// =================== reduce + bias + softmax + top-2 ===================
__global__ void __launch_bounds__(256) softmax_kernel(const float* __restrict__ bias,
                                                      float* __restrict__ out)
{
    const int b = blockIdx.x;
    const int t = threadIdx.x;
    __shared__ float sred[256];
    __shared__ int   sidx[256];

    float d = -INFINITY;
    if (t < NC) {
        float s = 0.0f;
#pragma unroll 8
        for (int ks = 0; ks < KS; ks++) s += g_part[(ks * NB + b) * BN + t];
        d = s + bias[t];
        out[b * NC + t] = d;
    }
    sred[t] = d;
    __syncthreads();
    for (int off = 128; off; off >>= 1) {
        if (t < off) sred[t] = fmaxf(sred[t], sred[t + off]);
        __syncthreads();
    }
    float m = sred[0];
    __syncthreads();

    float e = (t < NC) ? expf(__fsub_rn(d, m)) : 0.0f;
    sred[t] = e;
    __syncthreads();
    for (int off = 128; off; off >>= 1) {
        if (t < off) sred[t] = __fadd_rn(sred[t], sred[t + off]);
        __syncthreads();
    }
    float s = sred[0];
    __syncthreads();

    float sc = -INFINITY;
    if (t < NC) {
        sc = (t == 0) ? 0.0f : __fdiv_rn(e, s);
        g_scores_rm[b * NC + t] = sc;
    }
    // top-1 (ties -> lowest class)
    sred[t] = sc; sidx[t] = t;
    __syncthreads();
    for (int off = 128; off; off >>= 1) {
        if (t < off) {
            float ov = sred[t + off]; int oi = sidx[t + off];
            if (ov > sred[t] || (ov == sred[t] && oi < sidx[t])) { sred[t] = ov; sidx[t] = oi; }
        }
        __syncthreads();
    }
    int a1 = sidx[0];
    float v1 = sred[0];
    if (t == 0) { g_rowmax[b] = v1; g_rowarg[b] = a1; }
    __syncthreads();
    // top-2 excluding a1
    sred[t] = (t == a1) ? -INFINITY : sc;
    sidx[t] = t;
    __syncthreads();
    for (int off = 128; off; off >>= 1) {
        if (t < off) {
            float ov = sred[t + off]; int oi = sidx[t + off];
            if (ov > sred[t] || (ov == sred[t] && oi < sidx[t])) { sred[t] = ov; sidx[t] = oi; }
        }
        __syncthreads();
    }
    if (t == 0) { g_r2max[b] = sred[0]; g_r2arg[b] = sidx[0]; }
}

// =================== sequential greedy NMS (single WARP, SMEM state) ===================
__global__ void __launch_bounds__(32, 1) nms_kernel(float* __restrict__ out)
{
    __shared__ __align__(16) float rmax[NB];
    __shared__ float r2max[NB];
    __shared__ short rarg[NB];
    __shared__ short r2arg[NB];
    __shared__ unsigned zb[NB * 5];
    __shared__ unsigned char retired[NB];
    __shared__ short commits[NB];
    __shared__ short marked[NB];
    __shared__ int s_nm;

    const int l = threadIdx.x;

    for (int i = l; i < NB; i += 32) {
        rmax[i]  = g_rowmax[i]; rarg[i]  = (short)g_rowarg[i];
        r2max[i] = g_r2max[i];  r2arg[i] = (short)g_r2arg[i];
        retired[i] = 0; commits[i] = 0;
#pragma unroll
        for (int k = 0; k < 5; k++) zb[i * 5 + k] = 0;
    }
    if (l == 0) s_nm = 0;
    __syncwarp();

    for (int iter = 0; iter < NB; iter++) {
        // ---- lane-local top over its 16 rows (vectorized LDS) ----
        float v[16];
        const float4* rp = (const float4*)&rmax[l << 4];
#pragma unroll
        for (int k = 0; k < 4; k++) {
            float4 q = rp[k];
            v[4*k] = q.x; v[4*k+1] = q.y; v[4*k+2] = q.z; v[4*k+3] = q.w;
        }
        float b1 = v[0];
#pragma unroll
        for (int k = 1; k < 16; k++) b1 = fmaxf(b1, v[k]);

        // ---- global argmax via REDUX (ties -> lowest box) ----
        unsigned m1 = fmono(b1);
        unsigned gm = __reduce_max_sync(0xffffffffu, m1);
        unsigned bal = __ballot_sync(0xffffffffu, m1 == gm);
        int wl = __ffs(bal) - 1;
        int box = 0, cls = 0, idx = 0;
        if (l == wl) {
#pragma unroll
            for (int k = 15; k >= 0; k--) if (v[k] == b1) idx = k;
            box = (l << 4) + idx;
            cls = (int)rarg[box];
            commits[box] = (short)cls;
        }
        box = __shfl_sync(0xffffffffu, box, wl);
        cls = __shfl_sync(0xffffffffu, cls, wl);

        // ---- issue mask load early (one 64B line) ----
        const unsigned* mline = &g_masks16[(((size_t)cls * NB) + box) << 4];
        unsigned word = __ldg(&mline[l >> 1]);

        // ---- speculative prediction of next pivot + L1 prefetch (overlaps LDG) ----
        {
            float b2 = -2.0f;
            if (l == wl) {
#pragma unroll
                for (int k = 0; k < 16; k++) if (k != idx) b2 = fmaxf(b2, v[k]);
            }
            float cand = (l == wl) ? b2 : b1;
            unsigned cm = fmono(cand);
            unsigned gm2 = __reduce_max_sync(0xffffffffu, cm);
            unsigned bal2 = __ballot_sync(0xffffffffu, cm == gm2);
            int wl2 = __ffs(bal2) - 1;
            if (l == wl2) {
                int idx2 = 0;
#pragma unroll
                for (int k = 15; k >= 0; k--) {
                    bool excl = (l == wl) && (k == idx);
                    if (!excl && v[k] == cand) idx2 = k;
                }
                int bx2 = (l << 4) + idx2;
                int c2 = (int)rarg[bx2];
                const unsigned* pp = &g_masks16[(((size_t)c2 * NB) + bx2) << 4];
                asm volatile("prefetch.global.L1 [%0];" :: "l"(pp));
            }
        }

        // ---- state update (lane-owned rows; race-free) ----
        unsigned hits = (word >> ((l & 1) * 16)) & 0xFFFFu;
        const int owner = box >> 4;
        if (l == owner) hits &= ~(1u << (box & 15));
        const int cwi = cls >> 5;
        const unsigned cbm = 1u << (cls & 31);
        while (hits) {
            int i = __ffs(hits) - 1; hits &= hits - 1;
            int r = (l << 4) + i;
            if (retired[r]) {
                unsigned zw = zb[r * 5 + cwi];
                if (!(zw & cbm)) {                       // -1 -> 0 resurrection
                    zb[r * 5 + cwi] = zw | cbm;
                    if (rmax[r] < 0.0f) { rmax[r] = 0.0f; rarg[r] = (short)cls; }
                    else if (cls < (int)rarg[r]) rarg[r] = (short)cls;
                }
            } else if (cls != 0) {
                unsigned zw = zb[r * 5 + cwi];
                if (!(zw & cbm)) {                       // positive -> 0
                    zb[r * 5 + cwi] = zw | cbm;
                    if (cls == (int)rarg[r]) {
                        int sa = (int)r2arg[r];
                        if (sa >= 0) { rmax[r] = r2max[r]; rarg[r] = (short)sa; r2arg[r] = -1; }
                        else marked[atomicAdd(&s_nm, 1)] = (short)r;
                    } else if (cls == (int)r2arg[r]) {
                        r2arg[r] = -1;
                    }
                }
            }
        }
        if (l == owner) {                                // retire pivot
            retired[box] = 1; rmax[box] = -1.0f; rarg[box] = 0; r2arg[box] = -1;
#pragma unroll
            for (int k = 0; k < 5; k++) zb[box * 5 + k] = 0;
        }
        __syncwarp();

        // ---- rescans (rare): whole warp per marked row ----
        int nm = s_nm;
        if (nm) {
            for (int i = 0; i < nm; i++) {
                int mrow = (int)marked[i];
                const float* rowp = g_scores_rm + mrow * NC;
                float v1 = -1e30f, v2 = -1e30f; int c1 = 0x7fff, c2 = 0x7fff;
                for (int c = l; c < NC; c += 32) {
                    float sv = __ldg(&rowp[c]);
                    if (c == 0 || ((zb[mrow * 5 + (c >> 5)] >> (c & 31)) & 1u)) sv = 0.0f;
                    if (sv > v1) { v2 = v1; c2 = c1; v1 = sv; c1 = c; }
                    else if (sv > v2) { v2 = sv; c2 = c; }
                }
#pragma unroll
                for (int off = 16; off; off >>= 1) {
                    float o1 = __shfl_down_sync(0xffffffffu, v1, off);
                    float o2 = __shfl_down_sync(0xffffffffu, v2, off);
                    int  oc1 = __shfl_down_sync(0xffffffffu, c1, off);
                    int  oc2 = __shfl_down_sync(0xffffffffu, c2, off);
                    float cv; int cc;
                    if (o1 > v1 || (o1 == v1 && oc1 < c1)) { cv = v1; cc = c1; v1 = o1; c1 = oc1; }
                    else { cv = o1; cc = oc1; }
                    if (cv > v2 || (cv == v2 && cc < c2)) { v2 = cv; c2 = cc; }
                    if (o2 > v2 || (o2 == v2 && oc2 < c2)) { v2 = o2; c2 = oc2; }
                }
                if (l == 0) {
                    rmax[mrow] = v1; rarg[mrow] = (short)c1;
                    r2max[mrow] = v2; r2arg[mrow] = (short)c2;
                }
            }
            if (l == 0) s_nm = 0;
        }
        __syncwarp();
    }

    for (int i = l; i < NB; i += 32) out[NB * NC + i] = (float)commits[i];
}

// =================== launch ===================
extern "C" void kernel_launch(void* const* d_in, const int* in_sizes, int n_in,
                              void* d_out, int out_size) {
    const float* obj_fmap = (const float*)d_in[0];   // [512,4096]
    const float* boxes    = (const float*)d_in[1];   // [512,151,4]
    const float* W        = (const float*)d_in[2];   // [4096,151]
    const float* b        = (const float*)d_in[3];   // [151]
    float* out = (float*)d_out;                      // 77312 dists + 512 preds

    fused_gemm_mask<<<NC + 256, 256>>>(obj_fmap, W, boxes);
    softmax_kernel<<<NB, 256>>>(b, out);
    nms_kernel<<<1, 32>>>(out);
}

// round 5
// speedup vs baseline: 1.4781x; 1.1954x over previous
#include <cuda_runtime.h>
#include <math.h>
#include <stdint.h>

#define NB 512
#define NC 151
#define IN_DIM 4096
#define NMS_T 0.3f

#define KS 32            // k-splits
#define BKS (IN_DIM/KS)  // 128
#define BN 160           // padded N

// ---- device scratch (no allocations allowed) ----
__device__ float    g_part[KS * NB * BN];        // split-K partials
__device__ float    g_scores_rm[NB * NC];        // row-major softmax scores
__device__ unsigned g_masks16[NC * NB * 16];     // [c][box][w]: bit l of w = overlap(32w+l, box)
__device__ __align__(16) float g_t4val[NB * 4];  // per-row top-4 values (desc, cls asc)
__device__ int      g_t4cls[NB * 4];

// monotonic-uint mapping for float compare (handles the -1 sentinel)
__device__ __forceinline__ unsigned fmono(float v) {
    unsigned b = __float_as_uint(v);
    return (b & 0x80000000u) ? ~b : (b | 0x80000000u);
}
__device__ __forceinline__ float fmono_inv(float_t) = delete;
__device__ __forceinline__ float fmono_inv_u(unsigned u) {
    return (u & 0x80000000u) ? __uint_as_float(u ^ 0x80000000u) : __uint_as_float(~u);
}

// =================== fused: GEMM split-K partials + symmetric IoU masks ===================
__global__ void __launch_bounds__(256) fused_gemm_mask(
    const float* __restrict__ A, const float* __restrict__ W,
    const float* __restrict__ boxes)
{
    __shared__ union {
        struct { float As[8][65]; float Bs[8][BN]; } g;
        struct { float4 box[NB]; float area[NB]; } m;
    } sm;
    const int tid = threadIdx.x;

    if (blockIdx.x < NC) {
        // ---------------- mask path: one class per block, symmetric tiles ----------------
        const int c = blockIdx.x;
        const int lane = tid & 31, w = tid >> 5;
        for (int i = tid; i < NB; i += 256) {
            float4 v = ((const float4*)boxes)[i * NC + c];
            float bw = __fadd_rn(__fsub_rn(v.z, v.x), 1.0f);
            float bh = __fadd_rn(__fsub_rn(v.w, v.y), 1.0f);
            sm.m.box[i] = v;
            sm.m.area[i] = __fmul_rn(bw, bh);
        }
        __syncthreads();

        unsigned* gb = &g_masks16[(size_t)c * NB * 16];
        int tcnt = 0;
        for (int pb = 0; pb < 16; pb++) {
            for (int jb = pb; jb < 16; jb++, tcnt++) {
                if ((tcnt & 7) != w) continue;
                const int p = (pb << 5) + lane;
                const float4 pv = sm.m.box[p];
                const float par = sm.m.area[p];
                unsigned bword = 0, tmask = 0;
                for (int jj = 0; jj < 32; jj++) {
                    int j = (jb << 5) + jj;
                    float4 bv = sm.m.box[j];
                    float baj = sm.m.area[j];
                    float ix1 = fmaxf(pv.x, bv.x);
                    float iy1 = fmaxf(pv.y, bv.y);
                    float ix2 = fminf(pv.z, bv.z);
                    float iy2 = fminf(pv.w, bv.w);
                    float iw = fmaxf(__fadd_rn(__fsub_rn(ix2, ix1), 1.0f), 0.0f);
                    float ih = fmaxf(__fadd_rn(__fsub_rn(iy2, iy1), 1.0f), 0.0f);
                    float inter = __fmul_rn(iw, ih);
                    float uni = __fsub_rn(__fadd_rn(par, baj), inter);
                    float t3 = __fmul_rn(NMS_T, uni);
                    float diff = inter - t3;
                    bool pred = diff > 0.0f;
                    bool near = fabsf(diff) <= 1e-4f * t3;
                    if (__any_sync(0xffffffffu, near)) {
                        float q = __fdiv_rn(inter, uni);
                        if (near) pred = (q >= NMS_T);
                    }
                    unsigned word = __ballot_sync(0xffffffffu, pred);
                    if (lane == jj) bword = word;
                    tmask |= ((unsigned)pred) << jj;
                }
                gb[(((jb << 5) + lane) << 4) + pb] = bword;     // boxes in jb, pivot-bits pb
                if (jb != pb)
                    gb[(((pb << 5) + lane) << 4) + jb] = tmask; // boxes in pb, j-bits jb (symmetry)
            }
        }
    } else {
        // ---------------- gemm path (identical numerics) ----------------
        const int bi = blockIdx.x - NC;
        const int mt = bi >> 5;          // 0..7
        const int ks = bi & 31;          // 0..31
        const int tx = tid & 15, ty = tid >> 4;
        const int k0 = ks * BKS;

        float acc[4][10];
#pragma unroll
        for (int i = 0; i < 4; i++)
#pragma unroll
            for (int j = 0; j < 10; j++) acc[i][j] = 0.0f;

        for (int kc = 0; kc < BKS; kc += 8) {
#pragma unroll
            for (int r = 0; r < 2; r++) {
                int idx = tid + r * 256;
                int m = idx >> 3, kk = idx & 7;
                sm.g.As[kk][m] = A[(mt * 64 + m) * IN_DIM + k0 + kc + kk];
            }
#pragma unroll
            for (int r = 0; r < 5; r++) {
                int idx = tid + r * 256;
                int kk = idx / BN, n = idx % BN;
                sm.g.Bs[kk][n] = (n < NC) ? W[(k0 + kc + kk) * NC + n] : 0.0f;
            }
            __syncthreads();
#pragma unroll
            for (int kk = 0; kk < 8; kk++) {
                float a[4], b[10];
#pragma unroll
                for (int i = 0; i < 4; i++) a[i] = sm.g.As[kk][ty * 4 + i];
#pragma unroll
                for (int j = 0; j < 10; j++) b[j] = sm.g.Bs[kk][tx * 10 + j];
#pragma unroll
                for (int i = 0; i < 4; i++)
#pragma unroll
                    for (int j = 0; j < 10; j++) acc[i][j] = fmaf(a[i], b[j], acc[i][j]);
            }
            __syncthreads();
        }
#pragma unroll
        for (int i = 0; i < 4; i++) {
            int m = mt * 64 + ty * 4 + i;
#pragma unroll
            for (int j = 0; j < 10; j++) {
                int n = tx * 10 + j;
                g_part[(ks * NB + m) * BN + n] = acc[i][j];
            }
        }
    }
}

// =================== reduce + bias + softmax + exact top-4 ===================
__global__ void __launch_bounds__(256) softmax_kernel(const float* __restrict__ bias,
                                                      float* __restrict__ out)
{
    const int b = blockIdx.x;
    const int t = threadIdx.x;
    __shared__ float sred[256];
    __shared__ int   sidx[256];
    __shared__ int   s_win;

    float d = -INFINITY;
    if (t < NC) {
        float s = 0.0f;
#pragma unroll 8
        for (int ks = 0; ks < KS; ks++) s += g_part[(ks * NB + b) * BN + t];
        d = s + bias[t];
        out[b * NC + t] = d;
    }
    sred[t] = d;
    __syncthreads();
    for (int off = 128; off; off >>= 1) {
        if (t < off) sred[t] = fmaxf(sred[t], sred[t + off]);
        __syncthreads();
    }
    float m = sred[0];
    __syncthreads();

    float e = (t < NC) ? expf(__fsub_rn(d, m)) : 0.0f;
    sred[t] = e;
    __syncthreads();
    for (int off = 128; off; off >>= 1) {
        if (t < off) sred[t] = __fadd_rn(sred[t], sred[t + off]);
        __syncthreads();
    }
    float s = sred[0];
    __syncthreads();

    float sc = -INFINITY;
    if (t < NC) {
        sc = (t == 0) ? 0.0f : __fdiv_rn(e, s);
        g_scores_rm[b * NC + t] = sc;
    }

    // 4 argmax passes: (val desc, cls asc) with exclusion
    bool excl = false;
#pragma unroll
    for (int p = 0; p < 4; p++) {
        sred[t] = excl ? -INFINITY : sc;
        sidx[t] = t;
        __syncthreads();
        for (int off = 128; off; off >>= 1) {
            if (t < off) {
                float ov = sred[t + off]; int oi = sidx[t + off];
                if (ov > sred[t] || (ov == sred[t] && oi < sidx[t])) { sred[t] = ov; sidx[t] = oi; }
            }
            __syncthreads();
        }
        if (t == 0) {
            g_t4val[b * 4 + p] = sred[0];
            g_t4cls[b * 4 + p] = sidx[0];
            s_win = sidx[0];
        }
        __syncthreads();
        if (t == s_win) excl = true;
        __syncthreads();
    }
}

// =================== sequential greedy NMS (single warp, exact lookahead) ===================
__global__ void __launch_bounds__(32, 1) nms_kernel(float* __restrict__ out)
{
    __shared__ __align__(16) float rmax[NB];
    __shared__ __align__(16) float t4v[NB * 4];
    __shared__ __align__(8)  short t4c[NB * 4];
    __shared__ short rarg[NB];
    __shared__ unsigned zb[NB * 5];
    __shared__ unsigned char vb[NB];
    __shared__ unsigned char retired[NB];
    __shared__ short commits[NB];
    __shared__ short marked[NB];
    __shared__ int s_nm;

    const int l = threadIdx.x;

    for (int i = l; i < NB; i += 32) {
        float4 tv = *(const float4*)&g_t4val[i * 4];
        t4v[i * 4 + 0] = tv.x; t4v[i * 4 + 1] = tv.y;
        t4v[i * 4 + 2] = tv.z; t4v[i * 4 + 3] = tv.w;
#pragma unroll
        for (int k = 0; k < 4; k++) t4c[i * 4 + k] = (short)g_t4cls[i * 4 + k];
        rmax[i] = tv.x; rarg[i] = (short)g_t4cls[i * 4];
        vb[i] = 0xF; retired[i] = 0; commits[i] = 0;
#pragma unroll
        for (int k = 0; k < 5; k++) zb[i * 5 + k] = 0;
    }
    if (l == 0) s_nm = 0;
    __syncwarp();

    // ---- full argmax (branchless, all-lane) ----
    auto full_argmax = [&](int exclBox) -> int {
        float v[16];
        const float4* rp = (const float4*)&rmax[l << 4];
        float4 q0 = rp[0], q1 = rp[1], q2 = rp[2], q3 = rp[3];
        v[0]=q0.x; v[1]=q0.y; v[2]=q0.z; v[3]=q0.w;
        v[4]=q1.x; v[5]=q1.y; v[6]=q1.z; v[7]=q1.w;
        v[8]=q2.x; v[9]=q2.y; v[10]=q2.z; v[11]=q2.w;
        v[12]=q3.x; v[13]=q3.y; v[14]=q3.z; v[15]=q3.w;
        if (exclBox >= 0 && l == (exclBox >> 4)) v[exclBox & 15] = -2.0f;
        float a0 = fmaxf(v[0], v[1]),  a1 = fmaxf(v[2], v[3]);
        float a2 = fmaxf(v[4], v[5]),  a3 = fmaxf(v[6], v[7]);
        float a4 = fmaxf(v[8], v[9]),  a5 = fmaxf(v[10], v[11]);
        float a6 = fmaxf(v[12], v[13]), a7 = fmaxf(v[14], v[15]);
        float b0 = fmaxf(a0, a1), b1b = fmaxf(a2, a3);
        float b2 = fmaxf(a4, a5), b3 = fmaxf(a6, a7);
        float c0 = fmaxf(b0, b1b), c1 = fmaxf(b2, b3);
        float b1 = fmaxf(c0, c1);
        int idx = 15;
#pragma unroll
        for (int k = 15; k >= 0; k--) idx = (v[k] == b1) ? k : idx;
        unsigned m1 = fmono(b1);
        unsigned gm = __reduce_max_sync(0xffffffffu, m1);
        unsigned bal = __ballot_sync(0xffffffffu, m1 == gm);
        int wl = __ffs(bal) - 1;
        int boxl = (l << 4) + idx;
        return (__shfl_sync(0xffffffffu, boxl, wl) & 0xFFFF) | ((int)(gm > 0x80000000u) << 16);
    };

    // prologue
    int pack0 = full_argmax(-1);
    int box = pack0 & 0xFFFF;
    int cls = (int)rarg[box];
    unsigned word = __ldg(&g_masks16[(((size_t)cls * NB) + box) * 16 + (l >> 1)]);

    for (int iter = 0; iter < NB; iter++) {
        if (l == 0) commits[box] = (short)cls;
        const int owner = box >> 4;

        // ---- exact lookahead: argmax over pre-update state excluding pivot ----
        int spack = full_argmax(box);
        int sbox = spack & 0xFFFF;
        bool svalid = (spack >> 16) != 0;        // next value > 0 (also: sbox is a live row)
        int scls = (int)rarg[sbox];
        unsigned sword = __ldg(&g_masks16[(((size_t)scls * NB) + sbox) * 16 + (l >> 1)]);
        unsigned wsb = __shfl_sync(0xffffffffu, word, (sbox >> 5) << 1);
        bool sbox_hit = (wsb >> (sbox & 31)) & 1u;

        // ---- state update (lane-owned rows; race-free) ----
        const int cwi = cls >> 5;
        const unsigned cbm = 1u << (cls & 31);
        unsigned hits = (word >> ((l & 1) * 16)) & 0xFFFFu;
        unsigned selfm = (l == owner) ? (1u << (box & 15)) : 0u;
        hits &= ~selfm;
        while (hits) {
            int i = __ffs(hits) - 1; hits &= hits - 1;
            int r = (l << 4) + i;
            bool ret = retired[r] != 0;
            unsigned zw = zb[r * 5 + cwi];
            bool firstz = !(zw & cbm);
            if (!firstz) continue;
            if (ret) {
                zb[r * 5 + cwi] = zw | cbm;
                float rm = rmax[r];
                short ra = rarg[r];
                rmax[r] = (rm < 0.0f) ? 0.0f : rm;
                rarg[r] = (rm < 0.0f) ? (short)cls
                          : ((cls < (int)ra) ? (short)cls : ra);
            } else if (cls != 0) {
                zb[r * 5 + cwi] = zw | cbm;
                uint2 cp = *(const uint2*)&t4c[r * 4];
                int k = -1;
                k = ((short)(cp.y >> 16) == cls) ? 3 : k;
                k = ((short)(cp.y & 0xFFFF) == cls) ? 2 : k;
                k = ((short)(cp.x >> 16) == cls) ? 1 : k;
                k = ((short)(cp.x & 0xFFFF) == cls) ? 0 : k;
                if (k >= 0) {
                    unsigned vbm = vb[r];
                    if ((vbm >> k) & 1u) {
                        vbm &= ~(1u << k);
                        vb[r] = (unsigned char)vbm;
                        if (vbm) {
                            int h = __ffs(vbm) - 1;
                            rmax[r] = t4v[r * 4 + h];
                            rarg[r] = t4c[r * 4 + h];
                        } else {
                            marked[atomicAdd(&s_nm, 1)] = (short)r;
                        }
                    }
                }
            }
        }
        if (l == owner) {                                // retire pivot
            retired[box] = 1; rmax[box] = -1.0f; rarg[box] = 0; vb[box] = 0;
#pragma unroll
            for (int k = 0; k < 5; k++) zb[box * 5 + k] = 0;
        }
        __syncwarp();

        // ---- rescans (rare): refill top-4 of marked rows ----
        int nm = s_nm;
        if (nm) {
            for (int i = 0; i < nm; i++) {
                int r = (int)marked[i];
                float ev[5];
#pragma unroll
                for (int j = 0; j < 5; j++) {
                    int c = l + 32 * j;
                    float sv = -1e30f;
                    if (c < NC) {
                        sv = __ldg(&g_scores_rm[r * NC + c]);
                        if (c == 0 || ((zb[r * 5 + (c >> 5)] >> (c & 31)) & 1u)) sv = 0.0f;
                    }
                    ev[j] = sv;
                }
                unsigned taken = 0;
#pragma unroll
                for (int p = 0; p < 4; p++) {
                    float bv = -1e30f; int bj = -1;
#pragma unroll
                    for (int j = 0; j < 5; j++) {
                        bool can = !((taken >> j) & 1u) && (l + 32 * j < NC);
                        if (can && ev[j] > bv) { bv = ev[j]; bj = j; }
                    }
                    unsigned key = (bj >= 0) ? fmono(bv) : 0u;
                    unsigned gmx = __reduce_max_sync(0xffffffffu, key);
                    unsigned candc = (key == gmx && bj >= 0) ? (unsigned)(l + 32 * bj) : 0xFFFFFFFFu;
                    unsigned wc = __reduce_min_sync(0xffffffffu, candc);
                    float wv = fmono_inv_u(gmx);
                    if (l == (int)(wc & 31)) taken |= 1u << (wc >> 5);
                    if (l == 0) { t4v[r * 4 + p] = wv; t4c[r * 4 + p] = (short)wc; }
                }
                if (l == 0) {
                    rmax[r] = t4v[r * 4]; rarg[r] = t4c[r * 4]; vb[r] = 0xF;
                }
            }
            if (l == 0) s_nm = 0;
        }
        __syncwarp();

        // ---- validate lookahead / advance ----
        if (svalid && !sbox_hit) {
            box = sbox; cls = scls; word = sword;
        } else {
            int pk = full_argmax(-1);
            box = pk & 0xFFFF;
            cls = (int)rarg[box];
            word = __ldg(&g_masks16[(((size_t)cls * NB) + box) * 16 + (l >> 1)]);
        }
    }

    for (int i = l; i < NB; i += 32) out[NB * NC + i] = (float)commits[i];
}

// =================== launch ===================
extern "C" void kernel_launch(void* const* d_in, const int* in_sizes, int n_in,
                              void* d_out, int out_size) {
    const float* obj_fmap = (const float*)d_in[0];   // [512,4096]
    const float* boxes    = (const float*)d_in[1];   // [512,151,4]
    const float* W        = (const float*)d_in[2];   // [4096,151]
    const float* b        = (const float*)d_in[3];   // [151]
    float* out = (float*)d_out;                      // 77312 dists + 512 preds

    fused_gemm_mask<<<NC + 256, 256>>>(obj_fmap, W, boxes);
    softmax_kernel<<<NB, 256>>>(b, out);
    nms_kernel<<<1, 32>>>(out);
}

// round 6
// speedup vs baseline: 1.6546x; 1.1194x over previous
#include <cuda_runtime.h>
#include <math.h>
#include <stdint.h>

#define NB 512
#define NC 151
#define IN_DIM 4096
#define NMS_T 0.3f
#define FULL 0xffffffffu

#define KS 32            // k-splits
#define BKS (IN_DIM/KS)  // 128
#define BN 160           // padded N

// ---- device scratch (no allocations allowed) ----
__device__ float    g_part[KS * NB * BN];        // split-K partials
__device__ float    g_scores_rm[NB * NC];        // row-major softmax scores
__device__ unsigned g_masks16[NC * NB * 16];     // [c][box][w]: bit l of w = overlap(32w+l, box)
__device__ __align__(16) float g_t4val[NB * 4];  // per-row top-4 values (desc, cls asc)
__device__ int      g_t4cls[NB * 4];

// monotonic-uint mapping for float compare (handles the -1/-2 sentinels)
__device__ __forceinline__ unsigned fmono(float v) {
    unsigned b = __float_as_uint(v);
    return (b & 0x80000000u) ? ~b : (b | 0x80000000u);
}
__device__ __forceinline__ float fmono_inv_u(unsigned u) {
    return (u & 0x80000000u) ? __uint_as_float(u ^ 0x80000000u) : __uint_as_float(~u);
}

// =================== fused: GEMM split-K partials + symmetric IoU masks ===================
__global__ void __launch_bounds__(256) fused_gemm_mask(
    const float* __restrict__ A, const float* __restrict__ W,
    const float* __restrict__ boxes)
{
    __shared__ union {
        struct { float As[8][65]; float Bs[8][BN]; } g;
        struct { float4 box[NB]; float area[NB]; } m;
    } sm;
    const int tid = threadIdx.x;

    if (blockIdx.x < NC) {
        // ---------------- mask path: one class per block, symmetric tiles ----------------
        const int c = blockIdx.x;
        const int lane = tid & 31, w = tid >> 5;
        for (int i = tid; i < NB; i += 256) {
            float4 v = ((const float4*)boxes)[i * NC + c];
            float bw = __fadd_rn(__fsub_rn(v.z, v.x), 1.0f);
            float bh = __fadd_rn(__fsub_rn(v.w, v.y), 1.0f);
            sm.m.box[i] = v;
            sm.m.area[i] = __fmul_rn(bw, bh);
        }
        __syncthreads();

        unsigned* gb = &g_masks16[(size_t)c * NB * 16];
        int tcnt = 0;
        for (int pb = 0; pb < 16; pb++) {
            for (int jb = pb; jb < 16; jb++, tcnt++) {
                if ((tcnt & 7) != w) continue;
                const int p = (pb << 5) + lane;
                const float4 pv = sm.m.box[p];
                const float par = sm.m.area[p];
                unsigned bword = 0, tmask = 0;
                for (int jj = 0; jj < 32; jj++) {
                    int j = (jb << 5) + jj;
                    float4 bv = sm.m.box[j];
                    float baj = sm.m.area[j];
                    float ix1 = fmaxf(pv.x, bv.x);
                    float iy1 = fmaxf(pv.y, bv.y);
                    float ix2 = fminf(pv.z, bv.z);
                    float iy2 = fminf(pv.w, bv.w);
                    float iw = fmaxf(__fadd_rn(__fsub_rn(ix2, ix1), 1.0f), 0.0f);
                    float ih = fmaxf(__fadd_rn(__fsub_rn(iy2, iy1), 1.0f), 0.0f);
                    float inter = __fmul_rn(iw, ih);
                    float uni = __fsub_rn(__fadd_rn(par, baj), inter);
                    float t3 = __fmul_rn(NMS_T, uni);
                    float diff = inter - t3;
                    bool pred = diff > 0.0f;
                    bool near = fabsf(diff) <= 1e-4f * t3;
                    if (__any_sync(FULL, near)) {
                        float q = __fdiv_rn(inter, uni);
                        if (near) pred = (q >= NMS_T);
                    }
                    unsigned word = __ballot_sync(FULL, pred);
                    if (lane == jj) bword = word;
                    tmask |= ((unsigned)pred) << jj;
                }
                gb[(((jb << 5) + lane) << 4) + pb] = bword;     // boxes in jb, pivot-bits pb
                if (jb != pb)
                    gb[(((pb << 5) + lane) << 4) + jb] = tmask; // boxes in pb, j-bits jb (symmetry)
            }
        }
    } else {
        // ---------------- gemm path (identical numerics) ----------------
        const int bi = blockIdx.x - NC;
        const int mt = bi >> 5;          // 0..7
        const int ks = bi & 31;          // 0..31
        const int tx = tid & 15, ty = tid >> 4;
        const int k0 = ks * BKS;

        float acc[4][10];
#pragma unroll
        for (int i = 0; i < 4; i++)
#pragma unroll
            for (int j = 0; j < 10; j++) acc[i][j] = 0.0f;

        for (int kc = 0; kc < BKS; kc += 8) {
#pragma unroll
            for (int r = 0; r < 2; r++) {
                int idx = tid + r * 256;
                int m = idx >> 3, kk = idx & 7;
                sm.g.As[kk][m] = A[(mt * 64 + m) * IN_DIM + k0 + kc + kk];
            }
#pragma unroll
            for (int r = 0; r < 5; r++) {
                int idx = tid + r * 256;
                int kk = idx / BN, n = idx % BN;
                sm.g.Bs[kk][n] = (n < NC) ? W[(k0 + kc + kk) * NC + n] : 0.0f;
            }
            __syncthreads();
#pragma unroll
            for (int kk = 0; kk < 8; kk++) {
                float a[4], b[10];
#pragma unroll
                for (int i = 0; i < 4; i++) a[i] = sm.g.As[kk][ty * 4 + i];
#pragma unroll
                for (int j = 0; j < 10; j++) b[j] = sm.g.Bs[kk][tx * 10 + j];
#pragma unroll
                for (int i = 0; i < 4; i++)
#pragma unroll
                    for (int j = 0; j < 10; j++) acc[i][j] = fmaf(a[i], b[j], acc[i][j]);
            }
            __syncthreads();
        }
#pragma unroll
        for (int i = 0; i < 4; i++) {
            int m = mt * 64 + ty * 4 + i;
#pragma unroll
            for (int j = 0; j < 10; j++) {
                int n = tx * 10 + j;
                g_part[(ks * NB + m) * BN + n] = acc[i][j];
            }
        }
    }
}

// =================== reduce + bias + softmax + exact top-4 ===================
__global__ void __launch_bounds__(256) softmax_kernel(const float* __restrict__ bias,
                                                      float* __restrict__ out)
{
    const int b = blockIdx.x;
    const int t = threadIdx.x;
    __shared__ float sred[256];
    __shared__ int   sidx[256];
    __shared__ int   s_win;

    float d = -INFINITY;
    if (t < NC) {
        float s = 0.0f;
#pragma unroll 8
        for (int ks = 0; ks < KS; ks++) s += g_part[(ks * NB + b) * BN + t];
        d = s + bias[t];
        out[b * NC + t] = d;
    }
    sred[t] = d;
    __syncthreads();
    for (int off = 128; off; off >>= 1) {
        if (t < off) sred[t] = fmaxf(sred[t], sred[t + off]);
        __syncthreads();
    }
    float m = sred[0];
    __syncthreads();

    float e = (t < NC) ? expf(__fsub_rn(d, m)) : 0.0f;
    sred[t] = e;
    __syncthreads();
    for (int off = 128; off; off >>= 1) {
        if (t < off) sred[t] = __fadd_rn(sred[t], sred[t + off]);
        __syncthreads();
    }
    float s = sred[0];
    __syncthreads();

    float sc = -INFINITY;
    if (t < NC) {
        sc = (t == 0) ? 0.0f : __fdiv_rn(e, s);
        g_scores_rm[b * NC + t] = sc;
    }

    // 4 argmax passes: (val desc, cls asc) with exclusion
    bool excl = false;
#pragma unroll
    for (int p = 0; p < 4; p++) {
        sred[t] = excl ? -INFINITY : sc;
        sidx[t] = t;
        __syncthreads();
        for (int off = 128; off; off >>= 1) {
            if (t < off) {
                float ov = sred[t + off]; int oi = sidx[t + off];
                if (ov > sred[t] || (ov == sred[t] && oi < sidx[t])) { sred[t] = ov; sidx[t] = oi; }
            }
            __syncthreads();
        }
        if (t == 0) {
            g_t4val[b * 4 + p] = sred[0];
            g_t4cls[b * 4 + p] = sidx[0];
            s_win = sidx[0];
        }
        __syncthreads();
        if (t == s_win) excl = true;
        __syncthreads();
    }
}

// =================== sequential greedy NMS (single warp, register-resident) ===================
__global__ void __launch_bounds__(32, 1) nms_kernel(float* __restrict__ out)
{
    __shared__ short rarg[NB];
    __shared__ __align__(16) float t4v[NB * 4];
    __shared__ __align__(8)  short t4c[NB * 4];
    __shared__ unsigned zb[NB * 5];
    __shared__ unsigned char vb[NB];
    __shared__ unsigned char retired[NB];
    __shared__ short commits[NB];
    __shared__ short marked[NB];
    __shared__ int s_nm;

    const int l = threadIdx.x;
    float v[16];                       // register-resident rmax of owned rows

    // ---- init (each lane its own 16 rows) ----
#pragma unroll
    for (int k = 0; k < 16; k++) {
        int r = (l << 4) + k;
        float4 tv = *(const float4*)&g_t4val[r * 4];
        t4v[r * 4 + 0] = tv.x; t4v[r * 4 + 1] = tv.y;
        t4v[r * 4 + 2] = tv.z; t4v[r * 4 + 3] = tv.w;
        int4 tc = *(const int4*)&g_t4cls[r * 4];
        t4c[r * 4 + 0] = (short)tc.x; t4c[r * 4 + 1] = (short)tc.y;
        t4c[r * 4 + 2] = (short)tc.z; t4c[r * 4 + 3] = (short)tc.w;
        v[k] = tv.x;
        rarg[r] = (short)tc.x;
        vb[r] = 0xF; retired[r] = 0; commits[r] = 0;
#pragma unroll
        for (int q = 0; q < 5; q++) zb[r * 5 + q] = 0;
    }
    if (l == 0) s_nm = 0;
    __syncwarp();

    // ---- register argmax (all-lane, branchless) ----
    auto warp_argmax = [&](int exclBox, int& obox, bool& pos) {
        float tv[16];
        bool ex = (exclBox >= 0) && (l == (exclBox >> 4));
        int bi = exclBox & 15;
#pragma unroll
        for (int k = 0; k < 16; k++) tv[k] = (ex && k == bi) ? -2.0f : v[k];
        float a0 = fmaxf(tv[0], tv[1]),   a1 = fmaxf(tv[2], tv[3]);
        float a2 = fmaxf(tv[4], tv[5]),   a3 = fmaxf(tv[6], tv[7]);
        float a4 = fmaxf(tv[8], tv[9]),   a5 = fmaxf(tv[10], tv[11]);
        float a6 = fmaxf(tv[12], tv[13]), a7 = fmaxf(tv[14], tv[15]);
        float b0 = fmaxf(a0, a1), b1 = fmaxf(a2, a3);
        float b2 = fmaxf(a4, a5), b3 = fmaxf(a6, a7);
        float c0 = fmaxf(b0, b1), c1 = fmaxf(b2, b3);
        float bm = fmaxf(c0, c1);
        int idx = 15;
#pragma unroll
        for (int k = 15; k >= 0; k--) idx = (tv[k] == bm) ? k : idx;
        unsigned m1 = fmono(bm);
        unsigned gm = __reduce_max_sync(FULL, m1);
        unsigned bal = __ballot_sync(FULL, m1 == gm);
        int wl = __ffs(bal) - 1;
        obox = __shfl_sync(FULL, (l << 4) + idx, wl);
        pos = gm > 0x80000000u;        // value strictly > 0
    };

    // ---- branchless hit processing (predicated; mutates hits) ----
    auto process = [&](unsigned& hits, int cls, int cwi, unsigned cbm) {
        bool has = hits != 0;
        int i = has ? (__ffs(hits) - 1) : 0;
        hits &= hits - 1;
        int r = (l << 4) + i;
        unsigned zw = zb[r * 5 + cwi];
        bool firstz = !(zw & cbm);
        bool ret = retired[r] != 0;
        float rm = v[0];
#pragma unroll
        for (int k = 1; k < 16; k++) rm = (k == i) ? v[k] : rm;
        short ra = rarg[r];
        // retired path
        bool act_ret = has && firstz && ret;
        float nrm_ret = (rm < 0.0f) ? 0.0f : rm;
        short nra_ret = (rm < 0.0f) ? (short)cls : ((cls < (int)ra) ? (short)cls : ra);
        // live path
        bool livez = has && firstz && !ret && (cls != 0);
        uint2 cp = *(const uint2*)&t4c[r * 4];
        short c0 = (short)(cp.x & 0xFFFF), c1s = (short)(cp.x >> 16);
        short c2 = (short)(cp.y & 0xFFFF), c3 = (short)(cp.y >> 16);
        int k4 = -1;
        k4 = ((int)c3 == cls) ? 3 : k4;
        k4 = ((int)c2 == cls) ? 2 : k4;
        k4 = ((int)c1s == cls) ? 1 : k4;
        k4 = ((int)c0 == cls) ? 0 : k4;
        unsigned vbm = vb[r];
        bool inv = livez && (k4 >= 0) && ((vbm >> (k4 & 3)) & 1u);
        unsigned vbm2 = vbm & ~(1u << (k4 & 3));
        int h = __ffs(vbm2) - 1; int hh = (h < 0) ? 0 : h;
        float nrm_live = t4v[r * 4 + hh];
        short nra_live = t4c[r * 4 + hh];
        bool promote = inv && (vbm2 != 0);
        bool mark = inv && (vbm2 == 0);
        // predicated commits
        if (act_ret || livez) zb[r * 5 + cwi] = zw | cbm;
        if (inv) vb[r] = (unsigned char)vbm2;
        bool wr = act_ret || promote;
        float nv = act_ret ? nrm_ret : nrm_live;
        short na = act_ret ? nra_ret : nra_live;
        if (wr) rarg[r] = na;
#pragma unroll
        for (int k = 0; k < 16; k++) v[k] = (wr && k == i) ? nv : v[k];
        if (mark) marked[atomicAdd(&s_nm, 1)] = (short)r;
    };

    // ---- prologue ----
    int box; bool pos0;
    warp_argmax(-1, box, pos0);
    int cls = (int)rarg[box];
    unsigned word = __ldg(&g_masks16[(((size_t)cls * NB) + box) * 16 + (l >> 1)]);

    for (int iter = 0; iter < NB; iter++) {
        if (l == 0) commits[box] = (short)cls;
        const int owner = box >> 4;

        // ---- exact lookahead (pre-update argmax excluding pivot) ----
        int sbox; bool svalid;
        warp_argmax(box, sbox, svalid);
        int scls = (int)rarg[sbox];
        unsigned sword = __ldg(&g_masks16[(((size_t)scls * NB) + sbox) * 16 + (l >> 1)]);
        unsigned wsb = __shfl_sync(FULL, word, (sbox >> 5) << 1);
        bool sbox_hit = (wsb >> (sbox & 31)) & 1u;

        // ---- update phase ----
        const int cwi = cls >> 5;
        const unsigned cbm = 1u << (cls & 31);
        unsigned hits = (word >> ((l & 1) * 16)) & 0xFFFFu;
        if (l == owner) hits &= ~(1u << (box & 15));
        process(hits, cls, cwi, cbm);                 // peeled common pass
        while (__any_sync(FULL, hits))                // warp-uniform loop
            process(hits, cls, cwi, cbm);

        // retire pivot (owner lane; predicated stores)
        if (l == owner) {
            retired[box] = 1; rarg[box] = 0; vb[box] = 0;
#pragma unroll
            for (int q = 0; q < 5; q++) zb[box * 5 + q] = 0;
        }
        {
            int bi = box & 15;
            bool own = (l == owner);
#pragma unroll
            for (int k = 0; k < 16; k++) v[k] = (own && k == bi) ? -1.0f : v[k];
        }
        __syncwarp();

        // ---- rescans (rare): refill top-4 of marked rows ----
        int nm = s_nm;
        if (nm) {
            for (int i = 0; i < nm; i++) {
                int r = (int)marked[i];
                float ev[5];
#pragma unroll
                for (int j = 0; j < 5; j++) {
                    int c = l + 32 * j;
                    float sv = -1e30f;
                    if (c < NC) {
                        sv = __ldg(&g_scores_rm[r * NC + c]);
                        if (c == 0 || ((zb[r * 5 + (c >> 5)] >> (c & 31)) & 1u)) sv = 0.0f;
                    }
                    ev[j] = sv;
                }
                unsigned taken = 0;
                float wv0 = 0.0f; int wc0 = 0;
#pragma unroll
                for (int p = 0; p < 4; p++) {
                    float bv = -1e30f; int bj = -1;
#pragma unroll
                    for (int j = 0; j < 5; j++) {
                        bool can = !((taken >> j) & 1u) && (l + 32 * j < NC);
                        if (can && ev[j] > bv) { bv = ev[j]; bj = j; }
                    }
                    unsigned key = (bj >= 0) ? fmono(bv) : 0u;
                    unsigned gmx = __reduce_max_sync(FULL, key);
                    unsigned candc = (key == gmx && bj >= 0) ? (unsigned)(l + 32 * bj) : 0xFFFFFFFFu;
                    unsigned wc = __reduce_min_sync(FULL, candc);
                    float wv = fmono_inv_u(gmx);
                    if (l == (int)(wc & 31)) taken |= 1u << (wc >> 5);
                    if (l == 0) { t4v[r * 4 + p] = wv; t4c[r * 4 + p] = (short)wc; }
                    if (p == 0) { wv0 = wv; wc0 = (int)wc; }
                }
                if (l == 0) { rarg[r] = (short)wc0; vb[r] = 0xF; }
                {
                    int ro = r >> 4, ri = r & 15;
                    bool own = (l == ro);
#pragma unroll
                    for (int k = 0; k < 16; k++) v[k] = (own && k == ri) ? wv0 : v[k];
                }
            }
            if (l == 0) s_nm = 0;
            __syncwarp();
        }

        // ---- advance ----
        if (svalid && !sbox_hit) {
            box = sbox; cls = scls; word = sword;
        } else {
            bool p2;
            warp_argmax(-1, box, p2);
            cls = (int)rarg[box];
            word = __ldg(&g_masks16[(((size_t)cls * NB) + box) * 16 + (l >> 1)]);
        }
    }

    for (int i = l; i < NB; i += 32) out[NB * NC + i] = (float)commits[i];
}

// =================== launch ===================
extern "C" void kernel_launch(void* const* d_in, const int* in_sizes, int n_in,
                              void* d_out, int out_size) {
    const float* obj_fmap = (const float*)d_in[0];   // [512,4096]
    const float* boxes    = (const float*)d_in[1];   // [512,151,4]
    const float* W        = (const float*)d_in[2];   // [4096,151]
    const float* b        = (const float*)d_in[3];   // [151]
    float* out = (float*)d_out;                      // 77312 dists + 512 preds

    fused_gemm_mask<<<NC + 256, 256>>>(obj_fmap, W, boxes);
    softmax_kernel<<<NB, 256>>>(b, out);
    nms_kernel<<<1, 32>>>(out);
}

// round 7
// speedup vs baseline: 1.8089x; 1.0933x over previous
#include <cuda_runtime.h>
#include <math.h>
#include <stdint.h>

#define NB 512
#define NC 151
#define IN_DIM 4096
#define NMS_T 0.3f
#define FULL 0xffffffffu

#define KS 32            // k-splits
#define BKS (IN_DIM/KS)  // 128
#define BN 160           // padded N

// ---- device scratch (no allocations allowed) ----
__device__ float    g_part[KS * NB * BN];        // split-K partials
__device__ float    g_scores_rm[NB * NC];        // row-major softmax scores
__device__ unsigned g_masks16[NC * NB * 16];     // [c][box][w]: bit l of w = overlap(32w+l, box)
__device__ __align__(16) float g_t4val[NB * 4];  // per-row top-4 values (desc, cls asc)
__device__ int      g_t4cls[NB * 4];

// monotonic-uint mapping for float compare (handles the -1/-2 sentinels)
__device__ __forceinline__ unsigned fmono(float v) {
    unsigned b = __float_as_uint(v);
    return (b & 0x80000000u) ? ~b : (b | 0x80000000u);
}
__device__ __forceinline__ float fmono_inv_u(unsigned u) {
    return (u & 0x80000000u) ? __uint_as_float(u ^ 0x80000000u) : __uint_as_float(~u);
}

// =================== fused: GEMM split-K partials + symmetric IoU masks ===================
__global__ void __launch_bounds__(256) fused_gemm_mask(
    const float* __restrict__ A, const float* __restrict__ W,
    const float* __restrict__ boxes)
{
    __shared__ union {
        struct { float As[8][65]; float Bs[8][BN]; } g;
        struct { float4 box[NB]; float area[NB]; } m;
    } sm;
    const int tid = threadIdx.x;

    if (blockIdx.x < 2 * NC) {
        // -------- mask path: two blocks per class (16-way tile split) --------
        const int c = blockIdx.x >> 1;
        const int half16 = blockIdx.x & 1;
        const int lane = tid & 31, w = tid >> 5;
        const int w8 = w + 8 * half16;
        for (int i = tid; i < NB; i += 256) {
            float4 v = ((const float4*)boxes)[i * NC + c];
            float bw = __fadd_rn(__fsub_rn(v.z, v.x), 1.0f);
            float bh = __fadd_rn(__fsub_rn(v.w, v.y), 1.0f);
            sm.m.box[i] = v;
            sm.m.area[i] = __fmul_rn(bw, bh);
        }
        __syncthreads();

        unsigned* gb = &g_masks16[(size_t)c * NB * 16];
        int tcnt = 0;
        for (int pb = 0; pb < 16; pb++) {
            for (int jb = pb; jb < 16; jb++, tcnt++) {
                if ((tcnt & 15) != w8) continue;
                const int p = (pb << 5) + lane;
                const float4 pv = sm.m.box[p];
                const float par = sm.m.area[p];
                unsigned bword = 0, tmask = 0;
                for (int jj = 0; jj < 32; jj++) {
                    int j = (jb << 5) + jj;
                    float4 bv = sm.m.box[j];
                    float baj = sm.m.area[j];
                    float ix1 = fmaxf(pv.x, bv.x);
                    float iy1 = fmaxf(pv.y, bv.y);
                    float ix2 = fminf(pv.z, bv.z);
                    float iy2 = fminf(pv.w, bv.w);
                    float iw = fmaxf(__fadd_rn(__fsub_rn(ix2, ix1), 1.0f), 0.0f);
                    float ih = fmaxf(__fadd_rn(__fsub_rn(iy2, iy1), 1.0f), 0.0f);
                    float inter = __fmul_rn(iw, ih);
                    float uni = __fsub_rn(__fadd_rn(par, baj), inter);
                    float t3 = __fmul_rn(NMS_T, uni);
                    float diff = inter - t3;
                    bool pred = diff > 0.0f;
                    bool near = fabsf(diff) <= 1e-4f * t3;
                    if (__any_sync(FULL, near)) {
                        float q = __fdiv_rn(inter, uni);
                        if (near) pred = (q >= NMS_T);
                    }
                    unsigned word = __ballot_sync(FULL, pred);
                    if (lane == jj) bword = word;
                    tmask |= ((unsigned)pred) << jj;
                }
                gb[(((jb << 5) + lane) << 4) + pb] = bword;     // boxes in jb, pivot-bits pb
                if (jb != pb)
                    gb[(((pb << 5) + lane) << 4) + jb] = tmask; // boxes in pb, j-bits jb (symmetry)
            }
        }
    } else {
        // ---------------- gemm path (identical numerics) ----------------
        const int bi = blockIdx.x - 2 * NC;
        const int mt = bi >> 5;          // 0..7
        const int ks = bi & 31;          // 0..31
        const int tx = tid & 15, ty = tid >> 4;
        const int k0 = ks * BKS;

        float acc[4][10];
#pragma unroll
        for (int i = 0; i < 4; i++)
#pragma unroll
            for (int j = 0; j < 10; j++) acc[i][j] = 0.0f;

        for (int kc = 0; kc < BKS; kc += 8) {
#pragma unroll
            for (int r = 0; r < 2; r++) {
                int idx = tid + r * 256;
                int m = idx >> 3, kk = idx & 7;
                sm.g.As[kk][m] = A[(mt * 64 + m) * IN_DIM + k0 + kc + kk];
            }
#pragma unroll
            for (int r = 0; r < 5; r++) {
                int idx = tid + r * 256;
                int kk = idx / BN, n = idx % BN;
                sm.g.Bs[kk][n] = (n < NC) ? W[(k0 + kc + kk) * NC + n] : 0.0f;
            }
            __syncthreads();
#pragma unroll
            for (int kk = 0; kk < 8; kk++) {
                float a[4], b[10];
#pragma unroll
                for (int i = 0; i < 4; i++) a[i] = sm.g.As[kk][ty * 4 + i];
#pragma unroll
                for (int j = 0; j < 10; j++) b[j] = sm.g.Bs[kk][tx * 10 + j];
#pragma unroll
                for (int i = 0; i < 4; i++)
#pragma unroll
                    for (int j = 0; j < 10; j++) acc[i][j] = fmaf(a[i], b[j], acc[i][j]);
            }
            __syncthreads();
        }
#pragma unroll
        for (int i = 0; i < 4; i++) {
            int m = mt * 64 + ty * 4 + i;
#pragma unroll
            for (int j = 0; j < 10; j++) {
                int n = tx * 10 + j;
                g_part[(ks * NB + m) * BN + n] = acc[i][j];
            }
        }
    }
}

// =================== reduce + bias + softmax + exact top-4 ===================
__global__ void __launch_bounds__(256) softmax_kernel(const float* __restrict__ bias,
                                                      float* __restrict__ out)
{
    const int b = blockIdx.x;
    const int t = threadIdx.x;
    __shared__ float sred[256];
    __shared__ int   sidx[256];
    __shared__ int   s_win;

    float d = -INFINITY;
    if (t < NC) {
        float s = 0.0f;
#pragma unroll 8
        for (int ks = 0; ks < KS; ks++) s += g_part[(ks * NB + b) * BN + t];
        d = s + bias[t];
        out[b * NC + t] = d;
    }
    sred[t] = d;
    __syncthreads();
    for (int off = 128; off; off >>= 1) {
        if (t < off) sred[t] = fmaxf(sred[t], sred[t + off]);
        __syncthreads();
    }
    float m = sred[0];
    __syncthreads();

    float e = (t < NC) ? expf(__fsub_rn(d, m)) : 0.0f;
    sred[t] = e;
    __syncthreads();
    for (int off = 128; off; off >>= 1) {
        if (t < off) sred[t] = __fadd_rn(sred[t], sred[t + off]);
        __syncthreads();
    }
    float s = sred[0];
    __syncthreads();

    float sc = -INFINITY;
    if (t < NC) {
        sc = (t == 0) ? 0.0f : __fdiv_rn(e, s);
        g_scores_rm[b * NC + t] = sc;
    }

    // 4 argmax passes: (val desc, cls asc) with exclusion
    bool excl = false;
#pragma unroll
    for (int p = 0; p < 4; p++) {
        sred[t] = excl ? -INFINITY : sc;
        sidx[t] = t;
        __syncthreads();
        for (int off = 128; off; off >>= 1) {
            if (t < off) {
                float ov = sred[t + off]; int oi = sidx[t + off];
                if (ov > sred[t] || (ov == sred[t] && oi < sidx[t])) { sred[t] = ov; sidx[t] = oi; }
            }
            __syncthreads();
        }
        if (t == 0) {
            g_t4val[b * 4 + p] = sred[0];
            g_t4cls[b * 4 + p] = sidx[0];
            s_win = sidx[0];
        }
        __syncthreads();
        if (t == s_win) excl = true;
        __syncthreads();
    }
}

// =================== sequential greedy NMS (single warp, register-resident) ===================
__global__ void __launch_bounds__(32, 1) nms_kernel(float* __restrict__ out)
{
    __shared__ short rarg[NB];
    __shared__ __align__(16) float t4v[NB * 4];
    __shared__ __align__(8)  short t4c[NB * 4];
    __shared__ unsigned zb[NB * 5];
    __shared__ short commits[NB];
    __shared__ short marked[NB];
    __shared__ int s_nm;

    const int l = threadIdx.x;
    float v[16];                       // register-resident rmax of owned rows
    unsigned retm = 0, resm = 0;       // per-lane retired / resurrected bitmasks
    unsigned long long vbq = 0xFFFFFFFFFFFFFFFFull;   // 16 x 4-bit top-4 validity

    // ---- init (each lane its own 16 rows) ----
#pragma unroll
    for (int k = 0; k < 16; k++) {
        int r = (l << 4) + k;
        float4 tv = *(const float4*)&g_t4val[r * 4];
        t4v[r * 4 + 0] = tv.x; t4v[r * 4 + 1] = tv.y;
        t4v[r * 4 + 2] = tv.z; t4v[r * 4 + 3] = tv.w;
        int4 tc = *(const int4*)&g_t4cls[r * 4];
        t4c[r * 4 + 0] = (short)tc.x; t4c[r * 4 + 1] = (short)tc.y;
        t4c[r * 4 + 2] = (short)tc.z; t4c[r * 4 + 3] = (short)tc.w;
        v[k] = tv.x;
        rarg[r] = (short)tc.x;
        commits[r] = 0;
#pragma unroll
        for (int q = 0; q < 5; q++) zb[r * 5 + q] = 0;
    }
    if (l == 0) s_nm = 0;
    __syncwarp();

    // ---- register argmax (all-lane, branchless; grouped-OR tie index) ----
    auto warp_argmax = [&](int exclBox, int& obox, bool& pos) {
        float tv[16];
        bool ex = (exclBox >= 0) && (l == (exclBox >> 4));
        int bi = exclBox & 15;
#pragma unroll
        for (int k = 0; k < 16; k++) tv[k] = (ex && k == bi) ? -2.0f : v[k];
        float a0 = fmaxf(tv[0], tv[1]),   a1 = fmaxf(tv[2], tv[3]);
        float a2 = fmaxf(tv[4], tv[5]),   a3 = fmaxf(tv[6], tv[7]);
        float a4 = fmaxf(tv[8], tv[9]),   a5 = fmaxf(tv[10], tv[11]);
        float a6 = fmaxf(tv[12], tv[13]), a7 = fmaxf(tv[14], tv[15]);
        float b0 = fmaxf(a0, a1), b1 = fmaxf(a2, a3);
        float b2 = fmaxf(a4, a5), b3 = fmaxf(a6, a7);
        float c0 = fmaxf(b0, b1), c1 = fmaxf(b2, b3);
        float bm = fmaxf(c0, c1);
        // equality mask (grouped OR, shallow)
        unsigned g0 = (tv[0]==bm ? 1u:0u) | (tv[1]==bm ? 2u:0u) | (tv[2]==bm ? 4u:0u) | (tv[3]==bm ? 8u:0u);
        unsigned g1 = (tv[4]==bm ? 1u:0u) | (tv[5]==bm ? 2u:0u) | (tv[6]==bm ? 4u:0u) | (tv[7]==bm ? 8u:0u);
        unsigned g2 = (tv[8]==bm ? 1u:0u) | (tv[9]==bm ? 2u:0u) | (tv[10]==bm ? 4u:0u) | (tv[11]==bm ? 8u:0u);
        unsigned g3 = (tv[12]==bm ? 1u:0u) | (tv[13]==bm ? 2u:0u) | (tv[14]==bm ? 4u:0u) | (tv[15]==bm ? 8u:0u);
        unsigned eqm = g0 | (g1 << 4) | (g2 << 8) | (g3 << 12);
        int idx = __ffs(eqm) - 1;
        unsigned m1 = fmono(bm);
        unsigned gm = __reduce_max_sync(FULL, m1);
        unsigned bal = __ballot_sync(FULL, m1 == gm);
        int wl = __ffs(bal) - 1;
        obox = __shfl_sync(FULL, (l << 4) + idx, wl);
        pos = gm > 0x80000000u;        // value strictly > 0
    };

    // ---- branchless hit processing (no v reads; predicated commits) ----
    auto process = [&](unsigned& hits, int cls, int cwi, unsigned cbm) {
        bool has = hits != 0;
        int i = has ? (__ffs(hits) - 1) : 0;
        hits &= hits - 1;
        int r = (l << 4) + i;
        unsigned zw = zb[r * 5 + cwi];
        bool firstz = has && !(zw & cbm);
        bool ret = (retm >> i) & 1u;
        bool res = (resm >> i) & 1u;
        short ra = rarg[r];
        // retired path: new value always 0.0; arg = cls if fresh else min
        bool act_ret = firstz && ret;
        short nra_ret = (!res) ? (short)cls : ((cls < (int)ra) ? (short)cls : ra);
        // live path
        bool livez = firstz && !ret && (cls != 0);
        uint2 cp = *(const uint2*)&t4c[r * 4];
        short c0 = (short)(cp.x & 0xFFFF), c1s = (short)(cp.x >> 16);
        short c2 = (short)(cp.y & 0xFFFF), c3 = (short)(cp.y >> 16);
        int k4 = -1;
        k4 = ((int)c3 == cls) ? 3 : k4;
        k4 = ((int)c2 == cls) ? 2 : k4;
        k4 = ((int)c1s == cls) ? 1 : k4;
        k4 = ((int)c0 == cls) ? 0 : k4;
        unsigned vbm = (unsigned)(vbq >> (i * 4)) & 0xFu;
        bool inv = livez && (k4 >= 0) && ((vbm >> (k4 & 3)) & 1u);
        unsigned vbm2 = vbm & ~(1u << (k4 & 3));
        int h = __ffs(vbm2) - 1; int hh = (h < 0) ? 0 : h;
        float nrm_live = t4v[r * 4 + hh];
        short nra_live = t4c[r * 4 + hh];
        bool promote = inv && (vbm2 != 0);
        bool mark = inv && (vbm2 == 0);
        // predicated commits
        if (act_ret || livez) zb[r * 5 + cwi] = zw | cbm;
        if (act_ret) resm |= 1u << i;
        if (inv) vbq = (vbq & ~(0xFull << (i * 4))) | ((unsigned long long)vbm2 << (i * 4));
        bool wr = act_ret || promote;
        float nv = act_ret ? 0.0f : nrm_live;
        short na = act_ret ? nra_ret : nra_live;
        if (wr) rarg[r] = na;
#pragma unroll
        for (int k = 0; k < 16; k++) v[k] = (wr && k == i) ? nv : v[k];
        if (mark) marked[atomicAdd(&s_nm, 1)] = (short)r;
    };

    // ---- prologue ----
    int box; bool pos0;
    warp_argmax(-1, box, pos0);
    int cls = (int)rarg[box];
    unsigned word = __ldg(&g_masks16[(((size_t)cls * NB) + box) * 16 + (l >> 1)]);

    for (int iter = 0; iter < NB; iter++) {
        if (l == 0) commits[box] = (short)cls;
        const int owner = box >> 4;

        // ---- exact lookahead (pre-update argmax excluding pivot) ----
        int sbox; bool svalid;
        warp_argmax(box, sbox, svalid);
        int scls = (int)rarg[sbox];
        unsigned sword = __ldg(&g_masks16[(((size_t)scls * NB) + sbox) * 16 + (l >> 1)]);
        unsigned wsb = __shfl_sync(FULL, word, (sbox >> 5) << 1);
        bool sbox_hit = (wsb >> (sbox & 31)) & 1u;

        // ---- update phase ----
        const int cwi = cls >> 5;
        const unsigned cbm = 1u << (cls & 31);
        unsigned hits = (word >> ((l & 1) * 16)) & 0xFFFFu;
        if (l == owner) hits &= ~(1u << (box & 15));
        process(hits, cls, cwi, cbm);                 // peeled common pass
        while (__any_sync(FULL, hits))                // warp-uniform loop
            process(hits, cls, cwi, cbm);

        // retire pivot (owner lane; predicated)
        {
            int bi = box & 15;
            bool own = (l == owner);
            if (own) {
                retm |= 1u << bi;
                resm &= ~(1u << bi);
                vbq &= ~(0xFull << (bi * 4));
                rarg[box] = 0;
#pragma unroll
                for (int q = 0; q < 5; q++) zb[box * 5 + q] = 0;
            }
#pragma unroll
            for (int k = 0; k < 16; k++) v[k] = (own && k == bi) ? -1.0f : v[k];
        }
        __syncwarp();

        // ---- rescans (rare): refill top-4 of marked rows ----
        int nm = s_nm;
        if (nm) {
            for (int i = 0; i < nm; i++) {
                int r = (int)marked[i];
                float ev[5];
#pragma unroll
                for (int j = 0; j < 5; j++) {
                    int c = l + 32 * j;
                    float sv = -1e30f;
                    if (c < NC) {
                        sv = __ldg(&g_scores_rm[r * NC + c]);
                        if (c == 0 || ((zb[r * 5 + (c >> 5)] >> (c & 31)) & 1u)) sv = 0.0f;
                    }
                    ev[j] = sv;
                }
                unsigned taken = 0;
                float wv0 = 0.0f; int wc0 = 0;
#pragma unroll
                for (int p = 0; p < 4; p++) {
                    float bv = -1e30f; int bj = -1;
#pragma unroll
                    for (int j = 0; j < 5; j++) {
                        bool can = !((taken >> j) & 1u) && (l + 32 * j < NC);
                        if (can && ev[j] > bv) { bv = ev[j]; bj = j; }
                    }
                    unsigned key = (bj >= 0) ? fmono(bv) : 0u;
                    unsigned gmx = __reduce_max_sync(FULL, key);
                    unsigned candc = (key == gmx && bj >= 0) ? (unsigned)(l + 32 * bj) : 0xFFFFFFFFu;
                    unsigned wc = __reduce_min_sync(FULL, candc);
                    float wv = fmono_inv_u(gmx);
                    if (l == (int)(wc & 31)) taken |= 1u << (wc >> 5);
                    if (l == 0) { t4v[r * 4 + p] = wv; t4c[r * 4 + p] = (short)wc; }
                    if (p == 0) { wv0 = wv; wc0 = (int)wc; }
                }
                if (l == 0) rarg[r] = (short)wc0;
                {
                    int ro = r >> 4, ri = r & 15;
                    bool own = (l == ro);
                    if (own) vbq |= 0xFull << (ri * 4);
#pragma unroll
                    for (int k = 0; k < 16; k++) v[k] = (own && k == ri) ? wv0 : v[k];
                }
            }
            if (l == 0) s_nm = 0;
            __syncwarp();
        }

        // ---- advance ----
        if (svalid && !sbox_hit) {
            box = sbox; cls = scls; word = sword;
        } else {
            bool p2;
            warp_argmax(-1, box, p2);
            cls = (int)rarg[box];
            word = __ldg(&g_masks16[(((size_t)cls * NB) + box) * 16 + (l >> 1)]);
        }
    }

    for (int i = l; i < NB; i += 32) out[NB * NC + i] = (float)commits[i];
}

// =================== launch ===================
extern "C" void kernel_launch(void* const* d_in, const int* in_sizes, int n_in,
                              void* d_out, int out_size) {
    const float* obj_fmap = (const float*)d_in[0];   // [512,4096]
    const float* boxes    = (const float*)d_in[1];   // [512,151,4]
    const float* W        = (const float*)d_in[2];   // [4096,151]
    const float* b        = (const float*)d_in[3];   // [151]
    float* out = (float*)d_out;                      // 77312 dists + 512 preds

    fused_gemm_mask<<<2 * NC + 256, 256>>>(obj_fmap, W, boxes);
    softmax_kernel<<<NB, 256>>>(b, out);
    nms_kernel<<<1, 32>>>(out);
}